// round 1
// baseline (speedup 1.0000x reference)
#include <cuda_runtime.h>
#include <math.h>

#define N_NODES 50000
#define N_EDGES 800000
#define S_CH 32
#define V_CH 32
#define HID 64
#define ESC 50
#define SQRT3F 1.7320508075688772f
#define TP_NORM 0.125f            // 1/sqrt(64)
#define INV_SQRT32 0.17677669529663687f
#define INV_SQRT119 0.09166984970282113f

// Persistent node state + aggregation scratch (device globals: no allocation).
__device__ float g_xs[N_NODES * 32];
__device__ float g_xv[N_NODES * 96];   // layout [n][3][32] component-major
__device__ float g_aggs[N_NODES * 32];
__device__ float g_aggv[N_NODES * 96];

__device__ __forceinline__ float sigmoidf_(float x) {
    return 1.0f / (1.0f + __expf(-x));
}

__device__ __forceinline__ float warp_sum(float v) {
    #pragma unroll
    for (int o = 16; o > 0; o >>= 1) v += __shfl_xor_sync(0xFFFFFFFFu, v, o);
    return v;
}

// LayerNorm + SiLU on scalars, sigmoid gate on vectors. lane = channel index.
// stage32 is a per-warp 32-float smem buffer (clobbered; holds final s on exit).
__device__ __forceinline__ void warp_process(
    float& s, float& vx, float& vy, float& vz,
    int lane, float* stage32, int st,
    const float* __restrict__ lng, const float* __restrict__ lnb,
    const float* __restrict__ Gw, const float* __restrict__ Gb)
{
    float m = warp_sum(s) * (1.0f / 32.0f);
    float d = s - m;
    float var = warp_sum(d * d) * (1.0f / 32.0f);
    float sn = d * rsqrtf(var + 1e-5f) * __ldg(lng + st * 32 + lane) + __ldg(lnb + st * 32 + lane);
    float a = sn * sigmoidf_(sn);           // silu
    __syncwarp();
    stage32[lane] = a;
    __syncwarp();
    float g = __ldg(Gb + st * 32 + lane);
    const float* gw = Gw + st * 1024;
    #pragma unroll 8
    for (int i = 0; i < 32; i++) g += stage32[i] * __ldg(gw + i * 32 + lane);
    g = sigmoidf_(g);
    s = a;
    vx *= g; vy *= g; vz *= g;
}

// ---------------- node embedding + process stage 0 ----------------
__global__ void k_embed(const float* __restrict__ x, const float* __restrict__ deg,
                        const float* __restrict__ pos,
                        const float* __restrict__ Wes, const float* __restrict__ Wev,
                        const float* __restrict__ lng, const float* __restrict__ lnb,
                        const float* __restrict__ Gw, const float* __restrict__ Gb)
{
    __shared__ float sStage[4][32];
    int w = threadIdx.x >> 5, lane = threadIdx.x & 31;
    int n = blockIdx.x * 4 + w;
    if (n >= N_NODES) return;

    const float* xr = x + (size_t)n * 118;
    float acc = 0.0f;
    #pragma unroll 4
    for (int i = 0; i < 118; i++) acc += __ldg(xr + i) * __ldg(Wes + i * 32 + lane);
    acc += __ldg(deg + n) * __ldg(Wes + 118 * 32 + lane);
    float s = acc * INV_SQRT119;

    float wv = __ldg(Wev + lane);
    float px = __ldg(pos + n * 3 + 0), py = __ldg(pos + n * 3 + 1), pz = __ldg(pos + n * 3 + 2);
    float vx = px * wv, vy = py * wv, vz = pz * wv;

    warp_process(s, vx, vy, vz, lane, sStage[w], 0, lng, lnb, Gw, Gb);

    g_xs[n * 32 + lane] = s;
    g_xv[n * 96 + lane] = vx;
    g_xv[n * 96 + 32 + lane] = vy;
    g_xv[n * 96 + 64 + lane] = vz;
}

// ---------------- zero aggregation buffers ----------------
__global__ void k_zero()
{
    int stride = gridDim.x * blockDim.x;
    for (int i = blockIdx.x * blockDim.x + threadIdx.x; i < N_NODES * 32; i += stride)
        g_aggs[i] = 0.0f;
    for (int i = blockIdx.x * blockDim.x + threadIdx.x; i < N_NODES * 96; i += stride)
        g_aggv[i] = 0.0f;
}

// ---------------- edge kernel: TP + radial gate + scatter-add ----------------
__global__ void __launch_bounds__(128, 8) k_edge(
    const float* __restrict__ evec, const float* __restrict__ elen,
    const int* __restrict__ eidx,
    const float* __restrict__ Wss, const float* __restrict__ Wvs,
    const float* __restrict__ Wsv, const float* __restrict__ Wvv,
    const float* __restrict__ Rw, const float* __restrict__ Rb)
{
    __shared__ float sWss[1024], sWvs[1024], sWsv[1024], sWvv[1024]; // 16 KB
    __shared__ float sEl[4][50];
    __shared__ float sMs[4][32];
    __shared__ float sMv[4][3][32];
    __shared__ float sSc[4][128];

    int tid = threadIdx.x;
    for (int i = tid; i < 1024; i += 128) {
        sWss[i] = Wss[i]; sWvs[i] = Wvs[i]; sWsv[i] = Wsv[i]; sWvv[i] = Wvv[i];
    }
    __syncthreads();

    int w = tid >> 5, lane = tid & 31;
    int warp_global = blockIdx.x * 4 + w;
    int nwarps = gridDim.x * 4;

    float rb0 = __ldg(Rb + lane), rb1 = __ldg(Rb + 32 + lane);
    float rb2 = __ldg(Rb + 64 + lane), rb3 = __ldg(Rb + 96 + lane);

    for (int e = warp_global; e < N_EDGES; e += nwarps) {
        int src = __ldg(eidx + e);
        int dst = __ldg(eidx + N_EDGES + e);

        // gather source node state (coalesced; L2-resident)
        float ms  = g_xs[src * 32 + lane];
        float mvx = g_xv[src * 96 + lane];
        float mvy = g_xv[src * 96 + 32 + lane];
        float mvz = g_xv[src * 96 + 64 + lane];

        // edge direction
        size_t e3 = (size_t)e * 3;
        float ex = __ldg(evec + e3), ey = __ldg(evec + e3 + 1), ez = __ldg(evec + e3 + 2);
        float inv = rsqrtf(ex * ex + ey * ey + ez * ez);
        float rx = ex * inv, ry = ey * inv, rz = ez * inv;
        float Yx = SQRT3F * rx, Yy = SQRT3F * ry, Yz = SQRT3F * rz;

        __syncwarp();  // prior iteration fully consumed shared buffers
        sMs[w][lane] = ms;
        sMv[w][0][lane] = mvx; sMv[w][1][lane] = mvy; sMv[w][2][lane] = mvz;
        size_t eb = (size_t)e * ESC;
        sEl[w][lane] = __ldg(elen + eb + lane);
        if (lane < ESC - 32) sEl[w][32 + lane] = __ldg(elen + eb + 32 + lane);
        __syncwarp();

        // radial MLP: scale[128] = sigmoid(el @ Rw + Rb)
        float a0 = rb0, a1 = rb1, a2 = rb2, a3 = rb3;
        #pragma unroll 5
        for (int i = 0; i < ESC; i++) {
            float el = sEl[w][i];
            const float* rw = Rw + i * 128;
            a0 += el * __ldg(rw + lane);
            a1 += el * __ldg(rw + 32 + lane);
            a2 += el * __ldg(rw + 64 + lane);
            a3 += el * __ldg(rw + 96 + lane);
        }

        // tensor product
        float accS = 0.0f, accSV = 0.0f, avx = 0.0f, avy = 0.0f, avz = 0.0f;
        #pragma unroll 8
        for (int i = 0; i < 32; i++) {
            float msi = sMs[w][i];
            float mx = sMv[w][0][i], my = sMv[w][1][i], mz = sMv[w][2][i];
            float dot = mx * rx + my * ry + mz * rz;  // (mv . Y1)/sqrt3
            int o = i * 32 + lane;
            accS  += msi * sWss[o] + dot * sWvs[o];
            accSV += msi * sWsv[o];
            float wvv = sWvv[o];
            avx += mx * wvv; avy += my * wvv; avz += mz * wvv;
        }

        sSc[w][lane]       = sigmoidf_(a0);
        sSc[w][32 + lane]  = sigmoidf_(a1);
        sSc[w][64 + lane]  = sigmoidf_(a2);
        sSc[w][96 + lane]  = sigmoidf_(a3);
        __syncwarp();

        float outs = accS * TP_NORM * sSc[w][lane];
        float s0 = sSc[w][32 + 3 * lane];      // stride-3: conflict-free
        float s1 = sSc[w][33 + 3 * lane];
        float s2 = sSc[w][34 + 3 * lane];
        float ovx = (accSV * Yx + avx) * TP_NORM * s0;
        float ovy = (accSV * Yy + avy) * TP_NORM * s1;
        float ovz = (accSV * Yz + avz) * TP_NORM * s2;

        atomicAdd(&g_aggs[dst * 32 + lane], outs);
        atomicAdd(&g_aggv[dst * 96 + lane], ovx);
        atomicAdd(&g_aggv[dst * 96 + 32 + lane], ovy);
        atomicAdd(&g_aggv[dst * 96 + 64 + lane], ovz);
    }
}

// ---------------- node update: residual + o3.Linear + process ----------------
__global__ void k_node(const float* __restrict__ Ls, const float* __restrict__ Lv,
                       int stage,
                       const float* __restrict__ lng, const float* __restrict__ lnb,
                       const float* __restrict__ Gw, const float* __restrict__ Gb)
{
    __shared__ float sS[4][32];
    __shared__ float sV[4][3][32];
    int w = threadIdx.x >> 5, lane = threadIdx.x & 31;
    int n = blockIdx.x * 4 + w;
    if (n >= N_NODES) return;

    float hs  = g_xs[n * 32 + lane] + g_aggs[n * 32 + lane];
    float hvx = g_xv[n * 96 + lane]      + g_aggv[n * 96 + lane];
    float hvy = g_xv[n * 96 + 32 + lane] + g_aggv[n * 96 + 32 + lane];
    float hvz = g_xv[n * 96 + 64 + lane] + g_aggv[n * 96 + 64 + lane];

    sS[w][lane] = hs;
    sV[w][0][lane] = hvx; sV[w][1][lane] = hvy; sV[w][2][lane] = hvz;
    __syncwarp();

    float ns = 0.0f, nvx = 0.0f, nvy = 0.0f, nvz = 0.0f;
    #pragma unroll 8
    for (int i = 0; i < 32; i++) {
        int o = i * 32 + lane;
        ns += sS[w][i] * __ldg(Ls + o);
        float lw = __ldg(Lv + o);
        nvx += sV[w][0][i] * lw; nvy += sV[w][1][i] * lw; nvz += sV[w][2][i] * lw;
    }
    ns *= INV_SQRT32; nvx *= INV_SQRT32; nvy *= INV_SQRT32; nvz *= INV_SQRT32;
    __syncwarp();

    warp_process(ns, nvx, nvy, nvz, lane, sS[w], stage, lng, lnb, Gw, Gb);

    g_xs[n * 32 + lane] = ns;
    g_xv[n * 96 + lane] = nvx;
    g_xv[n * 96 + 32 + lane] = nvy;
    g_xv[n * 96 + 64 + lane] = nvz;
}

// ---------------- output head ----------------
__global__ void k_out(const float* __restrict__ Os, const float* __restrict__ Ov,
                      const float* __restrict__ lng, const float* __restrict__ lnb,
                      const float* __restrict__ Gw, const float* __restrict__ Gb,
                      const float* __restrict__ Psw, const float* __restrict__ Psb,
                      const float* __restrict__ Pvw, const float* __restrict__ Pvb,
                      float* __restrict__ out)
{
    __shared__ float sS[4][32];
    __shared__ float sV[4][3][32];
    int w = threadIdx.x >> 5, lane = threadIdx.x & 31;
    int n = blockIdx.x * 4 + w;
    if (n >= N_NODES) return;

    float hs  = g_xs[n * 32 + lane];
    float hvx = g_xv[n * 96 + lane];
    float hvy = g_xv[n * 96 + 32 + lane];
    float hvz = g_xv[n * 96 + 64 + lane];

    sS[w][lane] = hs;
    sV[w][0][lane] = hvx; sV[w][1][lane] = hvy; sV[w][2][lane] = hvz;
    __syncwarp();

    float ns = 0.0f, nvx = 0.0f, nvy = 0.0f, nvz = 0.0f;
    #pragma unroll 8
    for (int i = 0; i < 32; i++) {
        int o = i * 32 + lane;
        ns += sS[w][i] * __ldg(Os + o);
        float lw = __ldg(Ov + o);
        nvx += sV[w][0][i] * lw; nvy += sV[w][1][i] * lw; nvz += sV[w][2][i] * lw;
    }
    ns *= INV_SQRT32; nvx *= INV_SQRT32; nvy *= INV_SQRT32; nvz *= INV_SQRT32;
    __syncwarp();

    warp_process(ns, nvx, nvy, nvz, lane, sS[w], 3, lng, lnb, Gw, Gb);
    // sS[w] already holds final scalars; stage gated vectors
    __syncwarp();
    sV[w][0][lane] = nvx; sV[w][1][lane] = nvy; sV[w][2][lane] = nvz;
    __syncwarp();

    // projections: sc = s @ Psw + Psb; tok[k] = v[k] @ Pvw + Pvb + sc
    float sc0 = 0.0f, sc1 = 0.0f;
    float t00 = 0.0f, t01 = 0.0f, t10 = 0.0f, t11 = 0.0f, t20 = 0.0f, t21 = 0.0f;
    #pragma unroll 8
    for (int i = 0; i < 32; i++) {
        float si = sS[w][i];
        float vx = sV[w][0][i], vy = sV[w][1][i], vz = sV[w][2][i];
        float pw0 = __ldg(Psw + i * 64 + lane), pw1 = __ldg(Psw + i * 64 + 32 + lane);
        float qw0 = __ldg(Pvw + i * 64 + lane), qw1 = __ldg(Pvw + i * 64 + 32 + lane);
        sc0 += si * pw0; sc1 += si * pw1;
        t00 += vx * qw0; t01 += vx * qw1;
        t10 += vy * qw0; t11 += vy * qw1;
        t20 += vz * qw0; t21 += vz * qw1;
    }
    float base0 = sc0 + __ldg(Psb + lane) + __ldg(Pvb + lane);
    float base1 = sc1 + __ldg(Psb + 32 + lane) + __ldg(Pvb + 32 + lane);

    size_t ob = (size_t)n * 3 * 64;
    out[ob + lane]            = t00 + base0;
    out[ob + 32 + lane]       = t01 + base1;
    out[ob + 64 + lane]       = t10 + base0;
    out[ob + 96 + lane]       = t11 + base1;
    out[ob + 128 + lane]      = t20 + base0;
    out[ob + 160 + lane]      = t21 + base1;
}

extern "C" void kernel_launch(void* const* d_in, const int* in_sizes, int n_in,
                              void* d_out, int out_size)
{
    const float* x    = (const float*)d_in[0];
    const float* deg  = (const float*)d_in[1];
    const float* pos  = (const float*)d_in[2];
    const float* evec = (const float*)d_in[3];
    const float* elen = (const float*)d_in[4];
    const int*   eidx = (const int*)d_in[5];
    const float* Wes  = (const float*)d_in[6];
    const float* Wev  = (const float*)d_in[7];
    const float* Wss  = (const float*)d_in[8];
    const float* Wvs  = (const float*)d_in[9];
    const float* Wsv  = (const float*)d_in[10];
    const float* Wvv  = (const float*)d_in[11];
    const float* Ls   = (const float*)d_in[12];
    const float* Lv   = (const float*)d_in[13];
    const float* Rw   = (const float*)d_in[14];
    const float* Rb   = (const float*)d_in[15];
    const float* lng  = (const float*)d_in[16];
    const float* lnb  = (const float*)d_in[17];
    const float* Gw   = (const float*)d_in[18];
    const float* Gb   = (const float*)d_in[19];
    const float* Os   = (const float*)d_in[20];
    const float* Ov   = (const float*)d_in[21];
    const float* Psw  = (const float*)d_in[22];
    const float* Psb  = (const float*)d_in[23];
    const float* Pvw  = (const float*)d_in[24];
    const float* Pvb  = (const float*)d_in[25];
    float* out = (float*)d_out;

    int node_blocks = (N_NODES + 3) / 4;

    k_embed<<<node_blocks, 128>>>(x, deg, pos, Wes, Wev, lng, lnb, Gw, Gb);

    for (int l = 0; l < 2; l++) {
        k_zero<<<4096, 256>>>();
        k_edge<<<16384, 128>>>(evec, elen, eidx,
                               Wss + l * 1024, Wvs + l * 1024,
                               Wsv + l * 1024, Wvv + l * 1024,
                               Rw + l * ESC * 128, Rb + l * 128);
        k_node<<<node_blocks, 128>>>(Ls + l * 1024, Lv + l * 1024, l + 1,
                                     lng, lnb, Gw, Gb);
    }

    k_out<<<node_blocks, 128>>>(Os, Ov, lng, lnb, Gw, Gb, Psw, Psb, Pvw, Pvb, out);
}